// round 3
// baseline (speedup 1.0000x reference)
#include <cuda_runtime.h>

#define NN     8192
#define CHUNK  256
#define NCH    (NN / CHUNK)   // 32

// Scratch accumulators (device globals — allocation-free per harness rules)
static __device__ double             g_sum;   // sum of |dt| * log2(1+e^{-x}) over masked pairs (j>i)
static __device__ double             g_mse;   // sum of (p-t)^2
static __device__ unsigned long long g_cnt;   // masked-pair count

__global__ void rk_init() { g_sum = 0.0; g_mse = 0.0; g_cnt = 0ull; }

__device__ __forceinline__ float fast_ex2(float x) {
    float y; asm("ex2.approx.ftz.f32 %0, %1;" : "=f"(y) : "f"(x)); return y;
}
__device__ __forceinline__ float fast_lg2(float x) {
    float y; asm("lg2.approx.ftz.f32 %0, %1;" : "=f"(y) : "f"(x)); return y;
}

// Inner pair body:
//   dt  = t_i - t_j ; masked unless |dt| > 0.1
//   x   = sign(dt) * (p_i - p_j)
//   term = |dt| * log2(1 + 2^{-x*log2e})        (ln2 folded into finalize)
// pred is pre-scaled by log2e, so -x*log2e = (p_j' - p_i') with the sign of dt
// applied via a single sign-bit XOR.
__device__ __forceinline__ void pair_body(float ti, float pis, float2 v,
                                          float& sum, float& cnt) {
    float dt  = ti  - v.x;
    float dps = pis - v.y;
    // arg = -dps if dt >= 0, +dps if dt < 0   (== -sign(dt)*dps for masked pairs)
    unsigned sb  = (__float_as_uint(dt) & 0x80000000u) ^ 0x80000000u;
    float    arg = __uint_as_float(__float_as_uint(dps) ^ sb);
    float    l2  = fast_lg2(1.0f + fast_ex2(arg));
    float    adt = fabsf(dt);
    if (adt > 0.1f) { sum = fmaf(adt, l2, sum); cnt += 1.0f; }
}

__global__ __launch_bounds__(CHUNK) void rk_pairs(const float* __restrict__ pred,
                                                  const float* __restrict__ targ) {
    const int bi = blockIdx.y;   // i-chunk
    const int bj = blockIdx.x;   // j-chunk
    if (bj < bi) return;         // only pairs with j > i (symmetric term)

    __shared__ float2 s[CHUNK];          // (t_j, p_j * log2e)
    __shared__ float  red[3][CHUNK / 32];

    const float LOG2E = 1.4426950408889634f;
    const int t   = threadIdx.x;
    const int jg0 = bj * CHUNK;

    s[t] = make_float2(targ[jg0 + t], pred[jg0 + t] * LOG2E);

    const int   ig  = bi * CHUNK + t;
    const float ti  = targ[ig];
    const float pi  = pred[ig];
    const float pis = pi * LOG2E;
    __syncthreads();

    float sum = 0.0f, cnt = 0.0f, msq = 0.0f;

    if (bi == bj) {
        // Diagonal tile: also accumulate this chunk's MSE (covers all i exactly once).
        float dd = pi - ti;
        msq = dd * dd;
        #pragma unroll 4
        for (int j = t + 1; j < CHUNK; ++j)
            pair_body(ti, pis, s[j], sum, cnt);
    } else {
        #pragma unroll 8
        for (int j = 0; j < CHUNK; ++j)
            pair_body(ti, pis, s[j], sum, cnt);
    }

    // Warp reduce 3 values
    #pragma unroll
    for (int o = 16; o > 0; o >>= 1) {
        sum += __shfl_down_sync(0xffffffffu, sum, o);
        cnt += __shfl_down_sync(0xffffffffu, cnt, o);
        msq += __shfl_down_sync(0xffffffffu, msq, o);
    }
    const int lane = t & 31, warp = t >> 5;
    if (lane == 0) { red[0][warp] = sum; red[1][warp] = cnt; red[2][warp] = msq; }
    __syncthreads();

    if (t == 0) {
        float bs = 0.0f, bc = 0.0f, bm = 0.0f;
        #pragma unroll
        for (int w = 0; w < CHUNK / 32; ++w) {
            bs += red[0][w]; bc += red[1][w]; bm += red[2][w];
        }
        atomicAdd(&g_sum, (double)bs);
        atomicAdd(&g_cnt, (unsigned long long)(bc + 0.5f));
        if (bi == bj) atomicAdd(&g_mse, (double)bm);
    }
}

__global__ void rk_final(float* __restrict__ out) {
    double res = g_mse / (double)NN;                 // regression loss
    unsigned long long c = g_cnt;
    if (c > 0) {
        // ALPHA * ln2 * sum / cnt   (ln2 converts log2-domain softplus back)
        res += 3.0 * 0.6931471805599453 * g_sum / (double)c;
    }
    out[0] = (float)res;
}

extern "C" void kernel_launch(void* const* d_in, const int* in_sizes, int n_in,
                              void* d_out, int out_size) {
    const float* pred = (const float*)d_in[0];
    const float* targ = (const float*)d_in[1];
    float* out = (float*)d_out;
    (void)in_sizes; (void)n_in; (void)out_size;

    rk_init<<<1, 1>>>();
    dim3 grid(NCH, NCH);
    rk_pairs<<<grid, CHUNK>>>(pred, targ);
    rk_final<<<1, 1>>>(out);
}

// round 4
// speedup vs baseline: 1.0980x; 1.0980x over previous
#include <cuda_runtime.h>

#define NN        8192
#define CHUNK     128
#define NCH       (NN / CHUNK)        // 64
#define GRID_BLKS (NCH * NCH)         // 4096 launched blocks (lower-tri exit early)
#define LOG2E     1.4426950408889634f
#define LN2       0.6931471805599453

// Scratch accumulators (device globals — allocation-free per harness rules).
// Zero at load; the finalizing block resets them to zero after every run so
// each graph replay starts from a clean state (deterministic).
static __device__ double             g_sum  = 0.0;   // sum |dt| * log2(1+2^x) over masked pairs (j>i)
static __device__ double             g_mse  = 0.0;   // sum (p-t)^2
static __device__ unsigned long long g_cnt  = 0ull;  // masked-pair count
static __device__ unsigned int       g_done = 0u;    // completed-block counter

__device__ __forceinline__ float fast_ex2(float x) {
    float y; asm("ex2.approx.ftz.f32 %0, %1;" : "=f"(y) : "f"(x)); return y;
}
__device__ __forceinline__ float fast_lg2(float x) {
    float y; asm("lg2.approx.ftz.f32 %0, %1;" : "=f"(y) : "f"(x)); return y;
}

// Pair term, base-2 domain (pred pre-scaled by log2e, ln2 folded into finalize):
//   x  = -sign(dt) * dps           (single sign-bit LOP3)
//   t  = log2(1 + 2^x)             (EX2 + LG2, the 2 MUFU ops that set the floor)
//   if |dt| > 0.1: sum += |dt|*t, cnt += 1
__device__ __forceinline__ void pair_body(float ti, float pis, float tj, float pjs,
                                          float& sum, float& cnt) {
    float dt  = ti  - tj;
    float dps = pis - pjs;
    unsigned xb = __float_as_uint(dps) ^
                  ((__float_as_uint(dt) & 0x80000000u) ^ 0x80000000u);
    float u   = fast_ex2(__uint_as_float(xb));
    float l2  = fast_lg2(1.0f + u);
    float adt = fabsf(dt);
    if (adt > 0.1f) { sum = fmaf(adt, l2, sum); cnt += 1.0f; }
}

__global__ __launch_bounds__(CHUNK)
void rk_fused(const float* __restrict__ pred, const float* __restrict__ targ,
              float* __restrict__ out) {
    const int bi = blockIdx.y;          // i-chunk
    const int bj = blockIdx.x;          // j-chunk
    const int t  = threadIdx.x;

    __shared__ float4 s4[CHUNK / 2];    // packed (t0, p0s, t1, p1s)
    __shared__ float  red[3][CHUNK / 32];

    if (bj >= bi) {                     // upper triangle only (term is symmetric)
        float2* s2 = reinterpret_cast<float2*>(s4);
        const int jg = bj * CHUNK + t;
        s2[t] = make_float2(targ[jg], pred[jg] * LOG2E);

        const int   ig  = bi * CHUNK + t;
        const float ti  = targ[ig];
        const float pi  = pred[ig];
        const float pis = pi * LOG2E;
        __syncthreads();

        float sum = 0.0f, cnt = 0.0f, msq = 0.0f;

        if (bi == bj) {
            // Diagonal tile: j > i only; also fold in this chunk's MSE term.
            float dd = pi - ti;
            msq = dd * dd;
            #pragma unroll 4
            for (int j = t + 1; j < CHUNK; ++j) {
                float2 v = s2[j];
                pair_body(ti, pis, v.x, v.y, sum, cnt);
            }
        } else {
            // Off-diagonal: branch-free, 2 pairs per LDS.128.
            #pragma unroll 4
            for (int k = 0; k < CHUNK / 2; ++k) {
                float4 v = s4[k];
                pair_body(ti, pis, v.x, v.y, sum, cnt);
                pair_body(ti, pis, v.z, v.w, sum, cnt);
            }
        }

        // Block reduction: warp shuffles -> smem -> thread 0.
        #pragma unroll
        for (int o = 16; o > 0; o >>= 1) {
            sum += __shfl_down_sync(0xffffffffu, sum, o);
            cnt += __shfl_down_sync(0xffffffffu, cnt, o);
            msq += __shfl_down_sync(0xffffffffu, msq, o);
        }
        const int lane = t & 31, warp = t >> 5;
        if (lane == 0) { red[0][warp] = sum; red[1][warp] = cnt; red[2][warp] = msq; }
        __syncthreads();

        if (t == 0) {
            float bs = 0.0f, bc = 0.0f, bm = 0.0f;
            #pragma unroll
            for (int w = 0; w < CHUNK / 32; ++w) {
                bs += red[0][w]; bc += red[1][w]; bm += red[2][w];
            }
            atomicAdd(&g_sum, (double)bs);
            atomicAdd(&g_cnt, (unsigned long long)(bc + 0.5f));
            if (bi == bj) atomicAdd(&g_mse, (double)bm);
        }
    }

    // Last-block-finalizes: every launched block (working or not) arrives once.
    if (t == 0) {
        __threadfence();                               // make my atomics visible
        unsigned prev = atomicAdd(&g_done, 1u);
        if (prev == GRID_BLKS - 1) {
            double res = g_mse / (double)NN;           // regression loss
            unsigned long long c = g_cnt;
            if (c > 0) res += 3.0 * LN2 * g_sum / (double)c;
            out[0] = (float)res;
            // Reset for the next graph replay (kernel-boundary ordering
            // guarantees these land before any subsequent launch reads them).
            g_sum = 0.0; g_mse = 0.0; g_cnt = 0ull; g_done = 0u;
            __threadfence();
        }
    }
}

extern "C" void kernel_launch(void* const* d_in, const int* in_sizes, int n_in,
                              void* d_out, int out_size) {
    const float* pred = (const float*)d_in[0];
    const float* targ = (const float*)d_in[1];
    float* out = (float*)d_out;
    (void)in_sizes; (void)n_in; (void)out_size;

    dim3 grid(NCH, NCH);
    rk_fused<<<grid, CHUNK>>>(pred, targ, out);
}

// round 5
// speedup vs baseline: 1.1807x; 1.0753x over previous
#include <cuda_runtime.h>

#define NN     8192
#define TC     128                      // tile edge
#define NCH    (NN / TC)                // 64
#define NTILES (NCH * (NCH + 1) / 2)    // 2080 upper-tri tiles == grid size (single wave)
#define LOG2E  1.4426950408889634f
#define LN2    0.6931471805599453

// Scratch accumulators (device globals — allocation-free per harness rules).
// Zero at load; the finalizing block resets them after every run so each
// graph replay starts clean (deterministic).
static __device__ double             g_sum  = 0.0;   // sum |dt| * log2(1+2^x), masked pairs (j>i)
static __device__ double             g_mse  = 0.0;   // sum (p-t)^2
static __device__ unsigned long long g_cnt  = 0ull;  // masked-pair count
static __device__ unsigned int       g_done = 0u;    // completed-block counter

__device__ __forceinline__ float fast_ex2(float x) {
    float y; asm("ex2.approx.ftz.f32 %0, %1;" : "=f"(y) : "f"(x)); return y;
}
__device__ __forceinline__ float fast_lg2(float x) {
    float y; asm("lg2.approx.ftz.f32 %0, %1;" : "=f"(y) : "f"(x)); return y;
}

// tiles before row b (rows bi ≤ bj):  b*NCH - b(b-1)/2
__device__ __forceinline__ int tri_off(int b) { return b * NCH - (b * (b - 1)) / 2; }

// Pair term, base-2 domain (pred pre-scaled by log2e; ln2 folded into finalize).
// Minimal body: 2×FADD, 1×LOP3, 2×MUFU, 1×FADD, FSETP(|dt|), @p FFMA, @p FADD.
__device__ __forceinline__ void pair_body(float ti, float pis, float tj, float pjs,
                                          float& sum, float& cnt) {
    float dt  = ti  - tj;
    float dps = pis - pjs;
    // x = -sign(dt)*dps as one 3-input LOP3: dps ^ ((dt & signbit) ^ signbit)
    unsigned xb = __float_as_uint(dps) ^
                  ((__float_as_uint(dt) & 0x80000000u) ^ 0x80000000u);
    float u  = fast_ex2(__uint_as_float(xb));
    float l2 = fast_lg2(1.0f + u);
    if (fabsf(dt) > 0.1f) { sum = fmaf(fabsf(dt), l2, sum); cnt += 1.0f; }
}

__global__ __launch_bounds__(TC, 16)
void rk_fused(const float* __restrict__ pred, const float* __restrict__ targ,
              float* __restrict__ out) {
    // ── decode linear tile id -> (bi, bj), bi <= bj ──
    const int k = blockIdx.x;
    float disc = (float)((2 * NCH + 1) * (2 * NCH + 1) - 8 * k);
    int bi = (int)(((float)(2 * NCH + 1) - sqrtf(disc)) * 0.5f);
    if (bi < 0) bi = 0;
    if (bi > NCH - 1) bi = NCH - 1;
    while (bi + 1 <= NCH - 1 && tri_off(bi + 1) <= k) ++bi;   // fixup (<=1 iter)
    while (tri_off(bi) > k) --bi;
    const int bj = bi + (k - tri_off(bi));

    const int t = threadIdx.x;

    __shared__ float4 s4[TC / 2];          // packed (t0, p0s, t1, p1s)
    __shared__ float  red[3][TC / 32];

    float2* s2 = reinterpret_cast<float2*>(s4);
    const int jg = bj * TC + t;
    s2[t] = make_float2(targ[jg], pred[jg] * LOG2E);

    const int   ig  = bi * TC + t;
    const float ti  = targ[ig];
    const float pi  = pred[ig];
    const float pis = pi * LOG2E;
    __syncthreads();

    float sum = 0.0f, cnt = 0.0f, msq = 0.0f;

    if (bi == bj) {
        // Diagonal tile: j > i only; also fold in this chunk's MSE term.
        float dd = pi - ti;
        msq = dd * dd;
        #pragma unroll 4
        for (int j = t + 1; j < TC; ++j) {
            float2 v = s2[j];
            pair_body(ti, pis, v.x, v.y, sum, cnt);
        }
    } else {
        // Off-diagonal: branch-free, 2 pairs per LDS.128 (broadcast).
        #pragma unroll 16
        for (int q = 0; q < TC / 2; ++q) {
            float4 v = s4[q];
            pair_body(ti, pis, v.x, v.y, sum, cnt);
            pair_body(ti, pis, v.z, v.w, sum, cnt);
        }
    }

    // Block reduction: warp shuffles -> smem -> thread 0.
    #pragma unroll
    for (int o = 16; o > 0; o >>= 1) {
        sum += __shfl_down_sync(0xffffffffu, sum, o);
        cnt += __shfl_down_sync(0xffffffffu, cnt, o);
        msq += __shfl_down_sync(0xffffffffu, msq, o);
    }
    const int lane = t & 31, warp = t >> 5;
    if (lane == 0) { red[0][warp] = sum; red[1][warp] = cnt; red[2][warp] = msq; }
    __syncthreads();

    if (t == 0) {
        float bs = 0.0f, bc = 0.0f, bm = 0.0f;
        #pragma unroll
        for (int w = 0; w < TC / 32; ++w) {
            bs += red[0][w]; bc += red[1][w]; bm += red[2][w];
        }
        atomicAdd(&g_sum, (double)bs);
        atomicAdd(&g_cnt, (unsigned long long)(bc + 0.5f));
        if (bi == bj) atomicAdd(&g_mse, (double)bm);

        // Last-block-finalizes.
        __threadfence();
        unsigned prev = atomicAdd(&g_done, 1u);
        if (prev == NTILES - 1) {
            double res = g_mse / (double)NN;            // regression loss
            unsigned long long c = g_cnt;
            if (c > 0) res += 3.0 * LN2 * g_sum / (double)c;
            out[0] = (float)res;
            // Reset for the next graph replay.
            g_sum = 0.0; g_mse = 0.0; g_cnt = 0ull; g_done = 0u;
            __threadfence();
        }
    }
}

extern "C" void kernel_launch(void* const* d_in, const int* in_sizes, int n_in,
                              void* d_out, int out_size) {
    const float* pred = (const float*)d_in[0];
    const float* targ = (const float*)d_in[1];
    float* out = (float*)d_out;
    (void)in_sizes; (void)n_in; (void)out_size;

    rk_fused<<<NTILES, TC>>>(pred, targ, out);
}

// round 6
// speedup vs baseline: 1.1969x; 1.0137x over previous
#include <cuda_runtime.h>
#include <cstdint>

#define NN     8192
#define TC     128
#define NCH    (NN / TC)                 // 64
#define NTILES (NCH * (NCH + 1) / 2)     // 2080 upper-tri tiles
#define GRID   (148 * 8)                 // 1184 persistent blocks = one full wave
#define LOG2E  1.4426950408889634f
#define LN2    0.6931471805599453

// Device-global scratch (allocation-free). Finalizing block resets everything
// after each run so graph replays are deterministic.
static __device__ double             g_sum  = 0.0;
static __device__ double             g_mse  = 0.0;
static __device__ unsigned long long g_cnt  = 0ull;
static __device__ unsigned int       g_done = 0u;
static __device__ unsigned int       g_tile = GRID;   // next tile to hand out

__device__ __forceinline__ float fast_ex2(float x) {
    float y; asm("ex2.approx.ftz.f32 %0, %1;" : "=f"(y) : "f"(x)); return y;
}
__device__ __forceinline__ float fast_lg2(float x) {
    float y; asm("lg2.approx.ftz.f32 %0, %1;" : "=f"(y) : "f"(x)); return y;
}
__device__ __forceinline__ unsigned long long packf2(float lo, float hi) {
    unsigned long long r;
    asm("mov.b64 %0, {%1, %2};" : "=l"(r) : "f"(lo), "f"(hi));
    return r;
}

// tiles before row b (rows bi <= bj): b*NCH - b(b-1)/2
__device__ __forceinline__ int tri_off(int b) { return b * NCH - (b * (b - 1)) / 2; }

// Pair term, base-2 domain. njp holds (-tj, -pjs) so one packed f32x2 add
// yields (dt, dps). ~9 SASS instructions:
//   ADD.f32x2, LOP3(sign), LOP3(abs), MUFU.EX2, FADD, MUFU.LG2,
//   FSETP, @p FFMA, @p IADD
__device__ __forceinline__ void pair_body(unsigned long long ip, unsigned long long njp,
                                          float& sum, unsigned& cnt) {
    unsigned long long d;
    asm("add.rn.f32x2 %0, %1, %2;" : "=l"(d) : "l"(ip), "l"(njp));
    unsigned lo, hi;                                   // lo = dt, hi = dps (scaled)
    asm("mov.b64 {%0, %1}, %2;" : "=r"(lo), "=r"(hi) : "l"(d));
    unsigned xb = hi ^ ((lo & 0x80000000u) ^ 0x80000000u);   // -sign(dt)*dps
    float u   = fast_ex2(__uint_as_float(xb));
    float l2  = fast_lg2(1.0f + u);
    float adt = __uint_as_float(lo & 0x7fffffffu);           // |dt|
    if (adt > 0.1f) { sum = fmaf(adt, l2, sum); cnt += 1u; }
}

__global__ __launch_bounds__(TC, 8)
void rk_persist(const float* __restrict__ pred, const float* __restrict__ targ,
                float* __restrict__ out) {
    __shared__ unsigned long long s[TC];     // packed (-tj, -pjs)
    __shared__ float    red[3][TC / 32];
    __shared__ unsigned s_next;

    const int t = threadIdx.x;
    float sum = 0.0f, msq = 0.0f;
    unsigned cnt = 0u;

    unsigned tile = blockIdx.x;              // GRID < NTILES: every block starts with work
    while (tile < NTILES) {
        // decode linear tile id -> (bi, bj), bi <= bj
        const int k = (int)tile;
        float disc = (float)((2 * NCH + 1) * (2 * NCH + 1) - 8 * k);
        int bi = (int)(((float)(2 * NCH + 1) - sqrtf(disc)) * 0.5f);
        bi = min(max(bi, 0), NCH - 1);
        while (bi + 1 <= NCH - 1 && tri_off(bi + 1) <= k) ++bi;
        while (tri_off(bi) > k) --bi;
        const int bj = bi + (k - tri_off(bi));

        const int jg = bj * TC + t;
        const int ig = bi * TC + t;
        s[t] = packf2(-targ[jg], -pred[jg] * LOG2E);
        const float ti = targ[ig];
        const float pi = pred[ig];
        const unsigned long long ip = packf2(ti, pi * LOG2E);
        __syncthreads();

        if (bi == bj) {
            // Diagonal tile: j > i only; fold in this chunk's MSE (each i once).
            float dd = pi - ti;
            msq = fmaf(dd, dd, msq);
            #pragma unroll 4
            for (int j = t + 1; j < TC; ++j)
                pair_body(ip, s[j], sum, cnt);
        } else {
            // Off-diagonal: branch-free, 2 pairs per LDS.128 (broadcast).
            const ulonglong2* s2 = reinterpret_cast<const ulonglong2*>(s);
            #pragma unroll 8
            for (int q = 0; q < TC / 2; ++q) {
                ulonglong2 v = s2[q];
                pair_body(ip, v.x, sum, cnt);
                pair_body(ip, v.y, sum, cnt);
            }
        }

        // Grab next tile (greedy balance); sync also guards smem reuse.
        if (t == 0) s_next = atomicAdd(&g_tile, 1u);
        __syncthreads();
        tile = s_next;
    }

    // Per-block reduction (once per block, not per tile).
    float fc = (float)cnt;
    #pragma unroll
    for (int o = 16; o > 0; o >>= 1) {
        sum += __shfl_down_sync(0xffffffffu, sum, o);
        fc  += __shfl_down_sync(0xffffffffu, fc,  o);
        msq += __shfl_down_sync(0xffffffffu, msq, o);
    }
    const int lane = t & 31, warp = t >> 5;
    if (lane == 0) { red[0][warp] = sum; red[1][warp] = fc; red[2][warp] = msq; }
    __syncthreads();

    if (t == 0) {
        float bs = 0.0f, bc = 0.0f, bm = 0.0f;
        #pragma unroll
        for (int w = 0; w < TC / 32; ++w) {
            bs += red[0][w]; bc += red[1][w]; bm += red[2][w];
        }
        atomicAdd(&g_sum, (double)bs);
        atomicAdd(&g_cnt, (unsigned long long)(bc + 0.5f));
        if (bm != 0.0f) atomicAdd(&g_mse, (double)bm);

        // Last block finalizes + resets for the next graph replay.
        __threadfence();
        unsigned prev = atomicAdd(&g_done, 1u);
        if (prev == GRID - 1) {
            double res = g_mse / (double)NN;            // regression loss
            unsigned long long c = g_cnt;
            if (c > 0) res += 3.0 * LN2 * g_sum / (double)c;
            out[0] = (float)res;
            g_sum = 0.0; g_mse = 0.0; g_cnt = 0ull; g_done = 0u; g_tile = GRID;
            __threadfence();
        }
    }
}

extern "C" void kernel_launch(void* const* d_in, const int* in_sizes, int n_in,
                              void* d_out, int out_size) {
    const float* pred = (const float*)d_in[0];
    const float* targ = (const float*)d_in[1];
    float* out = (float*)d_out;
    (void)in_sizes; (void)n_in; (void)out_size;

    rk_persist<<<GRID, TC>>>(pred, targ, out);
}